// round 16
// baseline (speedup 1.0000x reference)
#include <cuda_runtime.h>
#include <cuda_bf16.h>
#include <cstdint>
#include <cstdio>

#define VOCAB 50257
#define EMB   64
#define HID   32
#define SEQL  256
#define BATCH 16
#define MROWS 4096          // SEQL*BATCH
#define GDIM  96            // 3*HID
#define KDIM  64            // 2*HID
#define NCHUNK 393          // 128-col chunks covering vocab (393*128 = 50304)
#define MBLK   32           // 4096/128
#define NB_PAD (NCHUNK * 16) // 6288 8-col blocks (padded)
#define PREPW_BLOCKS 3144    // NB_PAD*4*32/256
#define L2E 1.44269504f

// smem (float idx): pass A: As[0..4095] Bs[4096..8191] bias[8192..8319] rsum[8320..8575]
//                   pass B: As/Bs same; staging 128x128 = [0..16383]; bias[16384..16511] lse[16512..16639]
#define A_SM_FLOATS 8576     // 34304 B
#define B_SM_FLOATS 16640    // 66560 B

// ---------------- device scratch (static; no allocation) ----------------
__device__ float g_gx[2 * MROWS * GDIM];        // 3.1 MB  precomputed input gates
__device__ float g_h[MROWS * KDIM];             // 1 MB    concat hidden (fp32)
__device__ uint4 g_Ap[MBLK * 1024];             // 512 KB  A bf16 fragments
__device__ uint4 g_Ap2[MBLK * 1024];            // 512 KB  A*log2e fragments (pass A)
__device__ uint2 g_Bp[NB_PAD * 4 * 32];         // 6.4 MB  W bf16 fragments
__device__ float g_partial[MROWS * NCHUNK];     // 6.4 MB  per-chunk exp-sums
__device__ float g_lse[MROWS];

// ---------------- helpers ----------------
__device__ __forceinline__ uint32_t pack_bf16x2(float lo, float hi) {
    __nv_bfloat16 a = __float2bfloat16(lo), b = __float2bfloat16(hi);
    return (uint32_t)__bfloat16_as_ushort(a) | ((uint32_t)__bfloat16_as_ushort(b) << 16);
}
__device__ __forceinline__ float ex2(float x) {
    float r; asm("ex2.approx.f32 %0, %1;" : "=f"(r) : "f"(x)); return r;
}
__device__ __forceinline__ void mma_bf16(float c[4], const uint4 a, const uint2 b) {
    asm("mma.sync.aligned.m16n8k16.row.col.f32.bf16.bf16.f32 "
        "{%0,%1,%2,%3},{%4,%5,%6,%7},{%8,%9},{%0,%1,%2,%3};"
        : "+f"(c[0]), "+f"(c[1]), "+f"(c[2]), "+f"(c[3])
        : "r"(a.x), "r"(a.y), "r"(a.z), "r"(a.w), "r"(b.x), "r"(b.y));
}
__device__ __forceinline__ void cpasync16(uint32_t sdst, const void* gsrc) {
    asm volatile("cp.async.cg.shared.global [%0], [%1], 16;" :: "r"(sdst), "l"(gsrc));
}

// ---------------- launch 1: W->fragments (blocks < PREPW_BLOCKS) + gx (rest) ----------------
__global__ void k_prep(const float* __restrict__ W,
                       const int* __restrict__ tok, const float* __restrict__ emb,
                       const float* __restrict__ Wl, const float* __restrict__ bl,
                       const float* __restrict__ Wr, const float* __restrict__ br) {
    if (blockIdx.x < PREPW_BLOCKS) {
        int idx = blockIdx.x * 256 + threadIdx.x;   // NB_PAD*4*32
        int lane = idx & 31;
        int kb   = (idx >> 5) & 3;
        int nb   = idx >> 7;
        int g = lane >> 2, t = lane & 3;
        int col = nb * 8 + g;
        int k0 = kb * 16 + 2 * t;
        float w0 = 0.f, w1 = 0.f, w2 = 0.f, w3 = 0.f;
        if (col < VOCAB) {
            w0 = W[(size_t)k0 * VOCAB + col];
            w1 = W[(size_t)(k0 + 1) * VOCAB + col];
            w2 = W[(size_t)(k0 + 8) * VOCAB + col];
            w3 = W[(size_t)(k0 + 9) * VOCAB + col];
        }
        uint2 v;
        v.x = pack_bf16x2(w0, w1);
        v.y = pack_bf16x2(w2, w3);
        g_Bp[idx] = v;
        return;
    }
    // ---- gx: 256 blocks, threads 0..95 compute, all run barriers ----
    int bx = blockIdx.x - PREPW_BLOCKS;
    int j = threadIdx.x;
    int jj = (j < GDIM) ? j : 0;
    float wl[64], wr[64];
#pragma unroll
    for (int k = 0; k < 64; k++) {
        wl[k] = Wl[k * GDIM + jj];
        wr[k] = Wr[k * GDIM + jj];
    }
    float blv = bl[jj], brv = br[jj];
    __shared__ float xs[64];
    int p0 = bx * 16;
    for (int i = 0; i < 16; i++) {
        int p = p0 + i;
        int t = __ldg(&tok[p]);
        __syncthreads();
        if (j < 64) xs[j] = emb[t * EMB + j];
        __syncthreads();
        if (j < GDIM) {
            float a0 = blv, a1 = 0.f, r0 = brv, r1 = 0.f;
#pragma unroll
            for (int k = 0; k < 64; k += 2) {
                a0 = fmaf(xs[k],     wl[k],     a0);
                a1 = fmaf(xs[k + 1], wl[k + 1], a1);
                r0 = fmaf(xs[k],     wr[k],     r0);
                r1 = fmaf(xs[k + 1], wr[k + 1], r1);
            }
            g_gx[(size_t)p * GDIM + j]           = a0 + a1;
            g_gx[(size_t)(MROWS + p) * GDIM + j] = r0 + r1;
        }
    }
}

// ---------------- launch 2: warp-level GRU scan, one warp per (dir, batch) ----------------
__global__ void k_scan(const float* __restrict__ Wlhh, const float* __restrict__ blhh,
                       const float* __restrict__ Wrhh, const float* __restrict__ brhh) {
    int d = blockIdx.x >> 4, b = blockIdx.x & 15;
    int j = threadIdx.x;    // 0..31
    const float* Whh = d ? Wrhh : Wlhh;
    const float* bhh = d ? brhh : blhh;

    float wr_[32], wz_[32], wn_[32];
#pragma unroll
    for (int k = 0; k < 32; k++) {
        wr_[k] = Whh[k * GDIM + j];
        wz_[k] = Whh[k * GDIM + 32 + j];
        wn_[k] = Whh[k * GDIM + 64 + j];
    }
    float bhr = bhh[j], bhz = bhh[32 + j], bhn = bhh[64 + j];

    const float* gx = g_gx + (size_t)d * MROWS * GDIM;
    int s = d ? (SEQL - 1) : 0;
    int step = d ? -1 : 1;
    float h = 0.f;

    size_t idx = (size_t)(s * BATCH + b) * GDIM;
    float gxr = gx[idx + j], gxz = gx[idx + 32 + j], gxn = gx[idx + 64 + j];

    for (int i = 0; i < SEQL; i++) {
        float nr = 0.f, nz = 0.f, nn = 0.f;
        if (i < SEQL - 1) {
            size_t idx2 = (size_t)((s + step) * BATCH + b) * GDIM;
            nr = gx[idx2 + j]; nz = gx[idx2 + 32 + j]; nn = gx[idx2 + 64 + j];
        }
        float a0 = 0.f, a1 = 0.f, z0 = 0.f, z1 = 0.f, n0 = 0.f, n1 = 0.f;
#pragma unroll
        for (int k = 0; k < 32; k += 2) {
            float hk0 = __shfl_sync(0xffffffffu, h, k);
            float hk1 = __shfl_sync(0xffffffffu, h, k + 1);
            a0 = fmaf(hk0, wr_[k],     a0);
            a1 = fmaf(hk1, wr_[k + 1], a1);
            z0 = fmaf(hk0, wz_[k],     z0);
            z1 = fmaf(hk1, wz_[k + 1], z1);
            n0 = fmaf(hk0, wn_[k],     n0);
            n1 = fmaf(hk1, wn_[k + 1], n1);
        }
        float hr = a0 + a1 + bhr;
        float hz = z0 + z1 + bhz;
        float hn = n0 + n1 + bhn;
        float r = 1.f / (1.f + __expf(-(gxr + hr)));
        float z = 1.f / (1.f + __expf(-(gxz + hz)));
        float n = tanhf(gxn + r * hn);
        h = (1.f - z) * n + z * h;
        g_h[(size_t)(s * BATCH + b) * KDIM + d * HID + j] = h;
        gxr = nr; gxz = nz; gxn = nn;
        s += step;
    }
}

// ---------------- launch 3: A (h, 4096x64) -> bf16 frags, raw + log2e-scaled ----------------
__global__ void k_repack() {
    int idx = blockIdx.x * 256 + threadIdx.x;  // 256 mi * 4 kb * 32 = 32768
    int lane = idx & 31;
    int kb   = (idx >> 5) & 3;
    int mi   = idx >> 7;
    int g = lane >> 2, t = lane & 3;
    int row0 = mi * 16 + g;
    int k0 = kb * 16 + 2 * t;
    const float* h0 = g_h + (size_t)row0 * KDIM;
    const float* h8 = h0 + (size_t)8 * KDIM;
    float a0 = h0[k0], a1 = h0[k0 + 1], a2 = h0[k0 + 8], a3 = h0[k0 + 9];
    float b0 = h8[k0], b1 = h8[k0 + 1], b2 = h8[k0 + 8], b3 = h8[k0 + 9];
    uint4 v;
    v.x = pack_bf16x2(a0, a1); v.y = pack_bf16x2(b0, b1);
    v.z = pack_bf16x2(a2, a3); v.w = pack_bf16x2(b2, b3);
    g_Ap[idx] = v;
    uint4 v2;
    v2.x = pack_bf16x2(a0 * L2E, a1 * L2E); v2.y = pack_bf16x2(b0 * L2E, b1 * L2E);
    v2.z = pack_bf16x2(a2 * L2E, a3 * L2E); v2.w = pack_bf16x2(b2 * L2E, b3 * L2E);
    g_Ap2[idx] = v2;
}

// ---------------- GEMM: C = A(4096x64) * W(64xVOCAB), CTA tile 128x128 ----------------
// PASSB==0: per-row sum 2^(c + bias*log2e) -> g_partial (A pre-scaled by log2e)
// PASSB==1: out = logit + bias - lse; pipelined half-tile staging (stage1 overlaps store0)
template <int PASSB>
__global__ void __launch_bounds__(256, 2) k_gemm(const float* __restrict__ bias,
                                                 float* __restrict__ out) {
    extern __shared__ float smf[];
    uint4* As = (uint4*)smf;
    uint2* Bs = (uint2*)(smf + 4096);
    float* bias_s = smf + (PASSB ? 16384 : 8192);
    float* lse_s  = smf + 16512;   // pass B only
    float* rsum   = smf + 8320;    // pass A only

    int tid = threadIdx.x;
    int warp = tid >> 5, lane = tid & 31;
    int wm = warp & 3, wn = warp >> 2;
    int mb = blockIdx.y, ch = blockIdx.x;

    const uint4* Asrc = (PASSB ? g_Ap : g_Ap2) + (size_t)mb * 1024;
    const uint4* Bsrc = (const uint4*)(g_Bp + (size_t)ch * 2048);
    uint32_t sA = (uint32_t)__cvta_generic_to_shared(smf);
    uint32_t sB = (uint32_t)__cvta_generic_to_shared(smf + 4096);
#pragma unroll
    for (int i = 0; i < 4; i++) {
        cpasync16(sA + (tid + i * 256) * 16, Asrc + tid + i * 256);
        cpasync16(sB + (tid + i * 256) * 16, Bsrc + tid + i * 256);
    }
    asm volatile("cp.async.commit_group;");
    if (tid < 128) {
        int col = ch * 128 + tid;
        bias_s[tid] = (col < VOCAB) ? (PASSB ? bias[col] : bias[col] * L2E) : -1e30f;
        if (PASSB) lse_s[tid] = g_lse[mb * 128 + tid];
    }
    asm volatile("cp.async.wait_group 0;");
    __syncthreads();

    float c[2][8][4];
#pragma unroll
    for (int mf = 0; mf < 2; mf++)
#pragma unroll
        for (int nf = 0; nf < 8; nf++)
#pragma unroll
            for (int q = 0; q < 4; q++) c[mf][nf][q] = 0.f;

#pragma unroll
    for (int kb = 0; kb < 4; kb++) {
        uint4 a[2];
#pragma unroll
        for (int mf = 0; mf < 2; mf++)
            a[mf] = As[((wm * 2 + mf) * 4 + kb) * 32 + lane];
#pragma unroll
        for (int nf = 0; nf < 8; nf++) {
            uint2 b = Bs[((wn * 8 + nf) * 4 + kb) * 32 + lane];
            mma_bf16(c[0][nf], a[0], b);
            mma_bf16(c[1][nf], a[1], b);
        }
    }

    int g = lane >> 2, t = lane & 3;
    if (!PASSB) {
        float rs[2][2] = {{0.f, 0.f}, {0.f, 0.f}};
#pragma unroll
        for (int mf = 0; mf < 2; mf++)
#pragma unroll
            for (int nf = 0; nf < 8; nf++) {
                int cl = (wn * 8 + nf) * 8 + 2 * t;
                rs[mf][0] += ex2(c[mf][nf][0] + bias_s[cl]) + ex2(c[mf][nf][1] + bias_s[cl + 1]);
                rs[mf][1] += ex2(c[mf][nf][2] + bias_s[cl]) + ex2(c[mf][nf][3] + bias_s[cl + 1]);
            }
#pragma unroll
        for (int o = 1; o <= 2; o <<= 1) {
            rs[0][0] += __shfl_xor_sync(0xffffffffu, rs[0][0], o);
            rs[0][1] += __shfl_xor_sync(0xffffffffu, rs[0][1], o);
            rs[1][0] += __shfl_xor_sync(0xffffffffu, rs[1][0], o);
            rs[1][1] += __shfl_xor_sync(0xffffffffu, rs[1][1], o);
        }
        if (t == 0) {
#pragma unroll
            for (int mf = 0; mf < 2; mf++) {
                int rl = wm * 32 + mf * 16 + g;
                rsum[wn * 128 + rl]     = rs[mf][0];
                rsum[wn * 128 + rl + 8] = rs[mf][1];
            }
        }
        __syncthreads();
        if (tid < 128)
            g_partial[(size_t)(mb * 128 + tid) * NCHUNK + ch] = rsum[tid] + rsum[128 + tid];
    } else {
        // Pipelined half-tile staging. Half 0 = rows with (r&31)<16 (mf=0),
        // half 1 = rows with (r&31)>=16 (mf=1) — disjoint smem regions, so
        // stage(1) can overlap store(0) with no barrier between them.
        __syncthreads();                     // frag LDS complete before overwrite
        float* stg = smf;                    // 128 x 128, 64 KB
        int cbase = ch * 128;
        int colg  = tid & 127;
        int blkc  = colg & ~31;
        int gc    = cbase + colg;
        bool ok   = gc < VOCAB;
        size_t obase = (size_t)(mb * 128) * VOCAB + gc;

        // ---- stage half 0 (mf = 0) ----
        {
            int rloc = wm * 32 + g;
            int ca = 8 * (rloc & 3) + ((rloc >> 2) & 1);
            float l0 = lse_s[rloc], l1 = lse_s[rloc + 8];
#pragma unroll
            for (int nf = 0; nf < 8; nf++) {
                int cl = (wn * 8 + nf) * 8 + 2 * t;
                int blk = cl & ~31;
                int b0 = (cl + ca) & 31, b1 = (cl + 1 + ca) & 31;
                stg[rloc * 128 + blk + b0]       = c[0][nf][0] + bias_s[cl] - l0;
                stg[rloc * 128 + blk + b1]       = c[0][nf][1] + bias_s[cl + 1] - l0;
                stg[(rloc + 8) * 128 + blk + b0] = c[0][nf][2] + bias_s[cl] - l1;
                stg[(rloc + 8) * 128 + blk + b1] = c[0][nf][3] + bias_s[cl + 1] - l1;
            }
        }
        __syncthreads();
        // ---- stage half 1 (mf = 1) — issued first so STS overlaps store(0) ----
        {
            int rloc = wm * 32 + 16 + g;
            int ca = 8 * (rloc & 3) + ((rloc >> 2) & 1);
            float l0 = lse_s[rloc], l1 = lse_s[rloc + 8];
#pragma unroll
            for (int nf = 0; nf < 8; nf++) {
                int cl = (wn * 8 + nf) * 8 + 2 * t;
                int blk = cl & ~31;
                int b0 = (cl + ca) & 31, b1 = (cl + 1 + ca) & 31;
                stg[rloc * 128 + blk + b0]       = c[1][nf][0] + bias_s[cl] - l0;
                stg[rloc * 128 + blk + b1]       = c[1][nf][1] + bias_s[cl + 1] - l0;
                stg[(rloc + 8) * 128 + blk + b0] = c[1][nf][2] + bias_s[cl] - l1;
                stg[(rloc + 8) * 128 + blk + b1] = c[1][nf][3] + bias_s[cl + 1] - l1;
            }
        }
        // ---- store half 0: rows {32a + c : a<4, c<16} ----
#pragma unroll 8
        for (int i = 0; i < 32; i++) {
            int ridx = i * 2 + (tid >> 7);          // 0..63
            int row = 32 * (ridx >> 4) + (ridx & 15);
            int cr = 8 * (row & 3) + ((row >> 2) & 1);
            float v = stg[row * 128 + blkc + ((colg + cr) & 31)];
            if (ok) __stcs(&out[obase + (size_t)row * VOCAB], v);
        }
        __syncthreads();
        // ---- store half 1: rows {32a + 16 + c} ----
#pragma unroll 8
        for (int i = 0; i < 32; i++) {
            int ridx = i * 2 + (tid >> 7);
            int row = 32 * (ridx >> 4) + (ridx & 15) + 16;
            int cr = 8 * (row & 3) + ((row >> 2) & 1);
            float v = stg[row * 128 + blkc + ((colg + cr) & 31)];
            if (ok) __stcs(&out[obase + (size_t)row * VOCAB], v);
        }
    }
}

// ---------------- lse[row] = log(sum of chunk partials) ----------------
__global__ void k_lse() {
    int w = (blockIdx.x * blockDim.x + threadIdx.x) >> 5;   // row, 0..4095
    int lane = threadIdx.x & 31;
    float s = 0.f;
    for (int c = lane; c < NCHUNK; c += 32) s += g_partial[(size_t)w * NCHUNK + c];
#pragma unroll
    for (int o = 16; o; o >>= 1) s += __shfl_xor_sync(0xffffffffu, s, o);
    if (lane == 0) g_lse[w] = logf(s);
}

// ---------------- launch ----------------
extern "C" void kernel_launch(void* const* d_in, const int* in_sizes, int n_in,
                              void* d_out, int out_size) {
    const int*   tok    = (const int*)d_in[0];
    const float* emb    = (const float*)d_in[1];
    const float* W_out  = (const float*)d_in[2];
    const float* bias   = (const float*)d_in[3];
    const float* Wl_ih  = (const float*)d_in[4];
    const float* Wl_hh  = (const float*)d_in[5];
    const float* bl_ih  = (const float*)d_in[6];
    const float* bl_hh  = (const float*)d_in[7];
    const float* Wr_ih  = (const float*)d_in[8];
    const float* Wr_hh  = (const float*)d_in[9];
    const float* br_ih  = (const float*)d_in[10];
    const float* br_hh  = (const float*)d_in[11];
    float* out = (float*)d_out;

    const int smemA = A_SM_FLOATS * 4;   // 34304 B
    const int smemB = B_SM_FLOATS * 4;   // 66560 B
    cudaFuncSetAttribute(k_gemm<0>, cudaFuncAttributeMaxDynamicSharedMemorySize, smemA);
    cudaFuncSetAttribute(k_gemm<1>, cudaFuncAttributeMaxDynamicSharedMemorySize, smemB);

    k_prep<<<PREPW_BLOCKS + 256, 256>>>(W_out, tok, emb, Wl_ih, bl_ih, Wr_ih, br_ih); // 1
    k_scan<<<32, 32>>>(Wl_hh, bl_hh, Wr_hh, br_hh);                                   // 2
    k_repack<<<128, 256>>>();                                                         // 3
    dim3 gridG(NCHUNK, MBLK);
    k_gemm<0><<<gridG, 256, smemA>>>(bias, nullptr);                                  // 4 (ncu slot)
    k_lse<<<512, 256>>>();                                                            // 5
    k_gemm<1><<<gridG, 256, smemB>>>(bias, out);                                      // 6
}

// round 17
// speedup vs baseline: 1.1165x; 1.1165x over previous
#include <cuda_runtime.h>
#include <cuda_bf16.h>
#include <cstdint>
#include <cstdio>

#define VOCAB 50257
#define EMB   64
#define HID   32
#define SEQL  256
#define BATCH 16
#define MROWS 4096          // SEQL*BATCH
#define GDIM  96            // 3*HID
#define KDIM  64            // 2*HID
#define NCHUNK 393          // 128-col chunks covering vocab (393*128 = 50304)
#define MBLK   32           // 4096/128
#define NB_PAD (NCHUNK * 16) // 6288 8-col blocks (padded)
#define PREPW_BLOCKS 3144    // NB_PAD*4*32/256
#define L2E 1.44269504f

// smem (float idx): pass A: As[0..4095] Bs[4096..8191] bias[8192..8319] rsum[8320..8575]
//                   pass B: As/Bs same; staging 128x128 = [0..16383]; bias[16384..16511] lse[16512..16639]
#define A_SM_FLOATS 8576     // 34304 B
#define B_SM_FLOATS 16640    // 66560 B

// ---------------- device scratch (static; no allocation) ----------------
__device__ float g_gx[2 * MROWS * GDIM];        // 3.1 MB  precomputed input gates
__device__ float g_h[MROWS * KDIM];             // 1 MB    concat hidden (fp32)
__device__ uint4 g_Ap[MBLK * 1024];             // 512 KB  A bf16 fragments (both passes)
__device__ uint2 g_Bp[NB_PAD * 4 * 32];         // 6.4 MB  W bf16 fragments
__device__ float g_partial[MROWS * NCHUNK];     // 6.4 MB  per-chunk exp-sums
__device__ float g_lse[MROWS];

// ---------------- helpers ----------------
__device__ __forceinline__ uint32_t pack_bf16x2(float lo, float hi) {
    __nv_bfloat16 a = __float2bfloat16(lo), b = __float2bfloat16(hi);
    return (uint32_t)__bfloat16_as_ushort(a) | ((uint32_t)__bfloat16_as_ushort(b) << 16);
}
__device__ __forceinline__ float ex2(float x) {
    float r; asm("ex2.approx.f32 %0, %1;" : "=f"(r) : "f"(x)); return r;
}
__device__ __forceinline__ void mma_bf16(float c[4], const uint4 a, const uint2 b) {
    asm("mma.sync.aligned.m16n8k16.row.col.f32.bf16.bf16.f32 "
        "{%0,%1,%2,%3},{%4,%5,%6,%7},{%8,%9},{%0,%1,%2,%3};"
        : "+f"(c[0]), "+f"(c[1]), "+f"(c[2]), "+f"(c[3])
        : "r"(a.x), "r"(a.y), "r"(a.z), "r"(a.w), "r"(b.x), "r"(b.y));
}
__device__ __forceinline__ void cpasync16(uint32_t sdst, const void* gsrc) {
    asm volatile("cp.async.cg.shared.global [%0], [%1], 16;" :: "r"(sdst), "l"(gsrc));
}

// ---------------- launch 1: embedding + gx = x@W_ih + b_ih (both dirs) ----------------
__global__ void k_gx(const int* __restrict__ tok, const float* __restrict__ emb,
                     const float* __restrict__ Wl, const float* __restrict__ bl,
                     const float* __restrict__ Wr, const float* __restrict__ br) {
    int j = threadIdx.x;   // 0..95
    float wl[64], wr[64];
#pragma unroll
    for (int k = 0; k < 64; k++) {
        wl[k] = Wl[k * GDIM + j];
        wr[k] = Wr[k * GDIM + j];
    }
    float blv = bl[j], brv = br[j];
    __shared__ float xs[64];
    int p0 = blockIdx.x * 16;
    for (int i = 0; i < 16; i++) {
        int p = p0 + i;
        int t = __ldg(&tok[p]);
        __syncthreads();
        if (j < 64) xs[j] = emb[t * EMB + j];
        __syncthreads();
        float a0 = blv, a1 = 0.f, r0 = brv, r1 = 0.f;
#pragma unroll
        for (int k = 0; k < 64; k += 2) {
            a0 = fmaf(xs[k],     wl[k],     a0);
            a1 = fmaf(xs[k + 1], wl[k + 1], a1);
            r0 = fmaf(xs[k],     wr[k],     r0);
            r1 = fmaf(xs[k + 1], wr[k + 1], r1);
        }
        g_gx[(size_t)p * GDIM + j]           = a0 + a1;
        g_gx[(size_t)(MROWS + p) * GDIM + j] = r0 + r1;
    }
}

// ---------------- launch 2: warp GRU scan (blocks 0..31) + W repack (blocks 32..) ----------------
// Scan is latency-bound on 32 warps; W repack is BW-bound on 3144 blocks: overlap them.
__global__ void k_scan_prepw(const float* __restrict__ Wlhh, const float* __restrict__ blhh,
                             const float* __restrict__ Wrhh, const float* __restrict__ brhh,
                             const float* __restrict__ W) {
    if (blockIdx.x >= 32) {
        // ---- W (64 x VOCAB) -> bf16 B fragments ----
        int idx = (blockIdx.x - 32) * 256 + threadIdx.x;   // NB_PAD*4*32
        int lane = idx & 31;
        int kb   = (idx >> 5) & 3;
        int nb   = idx >> 7;
        int g = lane >> 2, t = lane & 3;
        int col = nb * 8 + g;
        int k0 = kb * 16 + 2 * t;
        float w0 = 0.f, w1 = 0.f, w2 = 0.f, w3 = 0.f;
        if (col < VOCAB) {
            w0 = W[(size_t)k0 * VOCAB + col];
            w1 = W[(size_t)(k0 + 1) * VOCAB + col];
            w2 = W[(size_t)(k0 + 8) * VOCAB + col];
            w3 = W[(size_t)(k0 + 9) * VOCAB + col];
        }
        uint2 v;
        v.x = pack_bf16x2(w0, w1);
        v.y = pack_bf16x2(w2, w3);
        g_Bp[idx] = v;
        return;
    }
    // ---- warp-level GRU scan: warp 0 of each block; lane j owns hidden unit j ----
    if (threadIdx.x >= 32) return;
    int d = blockIdx.x >> 4, b = blockIdx.x & 15;
    int j = threadIdx.x;    // 0..31
    const float* Whh = d ? Wrhh : Wlhh;
    const float* bhh = d ? brhh : blhh;

    float wr_[32], wz_[32], wn_[32];
#pragma unroll
    for (int k = 0; k < 32; k++) {
        wr_[k] = Whh[k * GDIM + j];
        wz_[k] = Whh[k * GDIM + 32 + j];
        wn_[k] = Whh[k * GDIM + 64 + j];
    }
    float bhr = bhh[j], bhz = bhh[32 + j], bhn = bhh[64 + j];

    const float* gx = g_gx + (size_t)d * MROWS * GDIM;
    int s = d ? (SEQL - 1) : 0;
    int step = d ? -1 : 1;
    float h = 0.f;

    size_t idx = (size_t)(s * BATCH + b) * GDIM;
    float gxr = gx[idx + j], gxz = gx[idx + 32 + j], gxn = gx[idx + 64 + j];

    for (int i = 0; i < SEQL; i++) {
        float nr = 0.f, nz = 0.f, nn = 0.f;
        if (i < SEQL - 1) {
            size_t idx2 = (size_t)((s + step) * BATCH + b) * GDIM;
            nr = gx[idx2 + j]; nz = gx[idx2 + 32 + j]; nn = gx[idx2 + 64 + j];
        }
        float a0 = 0.f, a1 = 0.f, z0 = 0.f, z1 = 0.f, n0 = 0.f, n1 = 0.f;
#pragma unroll
        for (int k = 0; k < 32; k += 2) {
            float hk0 = __shfl_sync(0xffffffffu, h, k);
            float hk1 = __shfl_sync(0xffffffffu, h, k + 1);
            a0 = fmaf(hk0, wr_[k],     a0);
            a1 = fmaf(hk1, wr_[k + 1], a1);
            z0 = fmaf(hk0, wz_[k],     z0);
            z1 = fmaf(hk1, wz_[k + 1], z1);
            n0 = fmaf(hk0, wn_[k],     n0);
            n1 = fmaf(hk1, wn_[k + 1], n1);
        }
        float hr = a0 + a1 + bhr;
        float hz = z0 + z1 + bhz;
        float hn = n0 + n1 + bhn;
        float r = 1.f / (1.f + __expf(-(gxr + hr)));
        float z = 1.f / (1.f + __expf(-(gxz + hz)));
        float n = tanhf(gxn + r * hn);
        h = (1.f - z) * n + z * h;
        g_h[(size_t)(s * BATCH + b) * KDIM + d * HID + j] = h;
        gxr = nr; gxz = nz; gxn = nn;
        s += step;
    }
}

// ---------------- launch 3: A (h, 4096x64) -> bf16 fragments ----------------
__global__ void k_repack() {
    int idx = blockIdx.x * 256 + threadIdx.x;  // 256 mi * 4 kb * 32 = 32768
    int lane = idx & 31;
    int kb   = (idx >> 5) & 3;
    int mi   = idx >> 7;
    int g = lane >> 2, t = lane & 3;
    int row0 = mi * 16 + g;
    int k0 = kb * 16 + 2 * t;
    const float* h0 = g_h + (size_t)row0 * KDIM;
    const float* h8 = h0 + (size_t)8 * KDIM;
    uint4 v;
    v.x = pack_bf16x2(h0[k0], h0[k0 + 1]);
    v.y = pack_bf16x2(h8[k0], h8[k0 + 1]);
    v.z = pack_bf16x2(h0[k0 + 8], h0[k0 + 9]);
    v.w = pack_bf16x2(h8[k0 + 8], h8[k0 + 9]);
    g_Ap[idx] = v;
}

// ---------------- GEMM: C = A(4096x64) * W(64xVOCAB), CTA tile 128x128 ----------------
// PASSB==0: per-row sum 2^(c*log2e + bias*log2e) -> g_partial (FFMA in epilogue)
// PASSB==1: out = logit + bias - lse via conflict-free swizzled staging + streaming stores
template <int PASSB>
__global__ void __launch_bounds__(256, 2) k_gemm(const float* __restrict__ bias,
                                                 float* __restrict__ out) {
    extern __shared__ float smf[];
    uint4* As = (uint4*)smf;
    uint2* Bs = (uint2*)(smf + 4096);
    float* bias_s = smf + (PASSB ? 16384 : 8192);
    float* lse_s  = smf + 16512;   // pass B only
    float* rsum   = smf + 8320;    // pass A only

    int tid = threadIdx.x;
    int warp = tid >> 5, lane = tid & 31;
    int wm = warp & 3, wn = warp >> 2;
    int mb = blockIdx.y, ch = blockIdx.x;

    const uint4* Asrc = g_Ap + (size_t)mb * 1024;
    const uint4* Bsrc = (const uint4*)(g_Bp + (size_t)ch * 2048);
    uint32_t sA = (uint32_t)__cvta_generic_to_shared(smf);
    uint32_t sB = (uint32_t)__cvta_generic_to_shared(smf + 4096);
#pragma unroll
    for (int i = 0; i < 4; i++) {
        cpasync16(sA + (tid + i * 256) * 16, Asrc + tid + i * 256);
        cpasync16(sB + (tid + i * 256) * 16, Bsrc + tid + i * 256);
    }
    asm volatile("cp.async.commit_group;");
    if (tid < 128) {
        int col = ch * 128 + tid;
        bias_s[tid] = (col < VOCAB) ? (PASSB ? bias[col] : bias[col] * L2E) : -1e30f;
        if (PASSB) lse_s[tid] = g_lse[mb * 128 + tid];
    }
    asm volatile("cp.async.wait_group 0;");
    __syncthreads();

    float c[2][8][4];
#pragma unroll
    for (int mf = 0; mf < 2; mf++)
#pragma unroll
        for (int nf = 0; nf < 8; nf++)
#pragma unroll
            for (int q = 0; q < 4; q++) c[mf][nf][q] = 0.f;

#pragma unroll
    for (int kb = 0; kb < 4; kb++) {
        uint4 a[2];
#pragma unroll
        for (int mf = 0; mf < 2; mf++)
            a[mf] = As[((wm * 2 + mf) * 4 + kb) * 32 + lane];
#pragma unroll
        for (int nf = 0; nf < 8; nf++) {
            uint2 b = Bs[((wn * 8 + nf) * 4 + kb) * 32 + lane];
            mma_bf16(c[0][nf], a[0], b);
            mma_bf16(c[1][nf], a[1], b);
        }
    }

    int g = lane >> 2, t = lane & 3;
    if (!PASSB) {
        float rs[2][2] = {{0.f, 0.f}, {0.f, 0.f}};
#pragma unroll
        for (int mf = 0; mf < 2; mf++)
#pragma unroll
            for (int nf = 0; nf < 8; nf++) {
                int cl = (wn * 8 + nf) * 8 + 2 * t;
                rs[mf][0] += ex2(fmaf(c[mf][nf][0], L2E, bias_s[cl]))
                           + ex2(fmaf(c[mf][nf][1], L2E, bias_s[cl + 1]));
                rs[mf][1] += ex2(fmaf(c[mf][nf][2], L2E, bias_s[cl]))
                           + ex2(fmaf(c[mf][nf][3], L2E, bias_s[cl + 1]));
            }
#pragma unroll
        for (int o = 1; o <= 2; o <<= 1) {
            rs[0][0] += __shfl_xor_sync(0xffffffffu, rs[0][0], o);
            rs[0][1] += __shfl_xor_sync(0xffffffffu, rs[0][1], o);
            rs[1][0] += __shfl_xor_sync(0xffffffffu, rs[1][0], o);
            rs[1][1] += __shfl_xor_sync(0xffffffffu, rs[1][1], o);
        }
        if (t == 0) {
#pragma unroll
            for (int mf = 0; mf < 2; mf++) {
                int rl = wm * 32 + mf * 16 + g;
                rsum[wn * 128 + rl]     = rs[mf][0];
                rsum[wn * 128 + rl + 8] = rs[mf][1];
            }
        }
        __syncthreads();
        if (tid < 128)
            g_partial[(size_t)(mb * 128 + tid) * NCHUNK + ch] = rsum[tid] + rsum[128 + tid];
    } else {
        // Conflict-free swizzled staging: addr = row*128 + (col&~31) + ((col + c(row)) & 31),
        // c(row) = 8*(row&3) + ((row>>2)&1). STS banks bijective per warp.
        __syncthreads();                     // frag LDS complete before overwrite
        float* stg = smf;                    // 128 x 128, 64 KB
#pragma unroll
        for (int mf = 0; mf < 2; mf++) {
            int rloc = wm * 32 + mf * 16 + g;
            int ca = 8 * (rloc & 3) + ((rloc >> 2) & 1);
            float l0 = lse_s[rloc], l1 = lse_s[rloc + 8];
#pragma unroll
            for (int nf = 0; nf < 8; nf++) {
                int cl = (wn * 8 + nf) * 8 + 2 * t;
                int blk = cl & ~31;
                int b0 = (cl + ca) & 31, b1 = (cl + 1 + ca) & 31;
                stg[rloc * 128 + blk + b0]       = c[mf][nf][0] + bias_s[cl] - l0;
                stg[rloc * 128 + blk + b1]       = c[mf][nf][1] + bias_s[cl + 1] - l0;
                stg[(rloc + 8) * 128 + blk + b0] = c[mf][nf][2] + bias_s[cl] - l1;
                stg[(rloc + 8) * 128 + blk + b1] = c[mf][nf][3] + bias_s[cl + 1] - l1;
            }
        }
        __syncthreads();
        int col = tid & 127;
        int blkc = col & ~31;
        int gc = ch * 128 + col;
        bool ok = gc < VOCAB;
        size_t obase = (size_t)(mb * 128) * VOCAB + gc;
#pragma unroll 8
        for (int i = 0; i < 64; i++) {
            int row = 2 * i + (tid >> 7);
            int cr = 8 * (row & 3) + ((row >> 2) & 1);
            float v = stg[row * 128 + blkc + ((col + cr) & 31)];
            if (ok) __stcs(&out[obase + (size_t)row * VOCAB], v);
        }
    }
}

// ---------------- lse[row] = log(sum of chunk partials) ----------------
__global__ void k_lse() {
    int w = (blockIdx.x * blockDim.x + threadIdx.x) >> 5;   // row, 0..4095
    int lane = threadIdx.x & 31;
    float s = 0.f;
    for (int c = lane; c < NCHUNK; c += 32) s += g_partial[(size_t)w * NCHUNK + c];
#pragma unroll
    for (int o = 16; o; o >>= 1) s += __shfl_xor_sync(0xffffffffu, s, o);
    if (lane == 0) g_lse[w] = logf(s);
}

// ---------------- launch ----------------
extern "C" void kernel_launch(void* const* d_in, const int* in_sizes, int n_in,
                              void* d_out, int out_size) {
    const int*   tok    = (const int*)d_in[0];
    const float* emb    = (const float*)d_in[1];
    const float* W_out  = (const float*)d_in[2];
    const float* bias   = (const float*)d_in[3];
    const float* Wl_ih  = (const float*)d_in[4];
    const float* Wl_hh  = (const float*)d_in[5];
    const float* bl_ih  = (const float*)d_in[6];
    const float* bl_hh  = (const float*)d_in[7];
    const float* Wr_ih  = (const float*)d_in[8];
    const float* Wr_hh  = (const float*)d_in[9];
    const float* br_ih  = (const float*)d_in[10];
    const float* br_hh  = (const float*)d_in[11];
    float* out = (float*)d_out;

    const int smemA = A_SM_FLOATS * 4;   // 34304 B
    const int smemB = B_SM_FLOATS * 4;   // 66560 B
    cudaFuncSetAttribute(k_gemm<0>, cudaFuncAttributeMaxDynamicSharedMemorySize, smemA);
    cudaFuncSetAttribute(k_gemm<1>, cudaFuncAttributeMaxDynamicSharedMemorySize, smemB);

    k_gx<<<MROWS / 16, 96>>>(tok, emb, Wl_ih, bl_ih, Wr_ih, br_ih);                   // 1
    k_scan_prepw<<<32 + PREPW_BLOCKS, 256>>>(Wl_hh, bl_hh, Wr_hh, br_hh, W_out);      // 2
    k_repack<<<128, 256>>>();                                                         // 3
    dim3 gridG(NCHUNK, MBLK);
    k_gemm<0><<<gridG, 256, smemA>>>(bias, nullptr);                                  // 4 (ncu slot)
    k_lse<<<512, 256>>>();                                                            // 5
    k_gemm<1><<<gridG, 256, smemB>>>(bias, out);                                      // 6
}